// round 5
// baseline (speedup 1.0000x reference)
#include <cuda_runtime.h>
#include <cuda_fp16.h>
#include <cstdint>

#define NN 8192
#define MM 8192
#define HD 64
#define NH 4
#define LOG2E 1.4426950408889634f

// ---- scratch (device globals; no allocations allowed) ----
__device__ float g_s[NH * NN];                      // pre-scaled by log2e
__device__ float g_d[NH * MM];                      // pre-scaled by log2e
__device__ float g_wfa[NH * 128];
// E1 in e4m3, MMA-fragment layout: [h][ch(128)][mb(2)][lane(32)][j8(8)][reg(2)] u32
__device__ uint32_t g_E1q[(size_t)NH * 128 * 1024];   // 2 MB
__device__ uint32_t g_AbT[(size_t)(MM / 32) * NN];    // [m/32][n] 8MB
__device__ float g_np[NH][NN][HD];                    // per-head numerators 8MB
__device__ float g_zp[NH][NN];                        // per-head Z

__device__ __forceinline__ uint32_t hadd2u(uint32_t a, uint32_t b) {
    uint32_t r; asm("add.f16x2 %0,%1,%2;" : "=r"(r) : "r"(a), "r"(b)); return r;
}
__device__ __forceinline__ uint32_t hmul2u(uint32_t a, uint32_t b) {
    uint32_t r; asm("mul.f16x2 %0,%1,%2;" : "=r"(r) : "r"(a), "r"(b)); return r;
}
__device__ __forceinline__ uint32_t hmax2u(uint32_t a, uint32_t b) {
    uint32_t r; asm("max.f16x2 %0,%1,%2;" : "=r"(r) : "r"(a), "r"(b)); return r;
}
__device__ __forceinline__ uint32_t ex2h2(uint32_t a) {
    uint32_t r; asm("ex2.approx.f16x2 %0,%1;" : "=r"(r) : "r"(a)); return r;
}
// leaky_relu then exp2 on packed f16x2
__device__ __forceinline__ uint32_t wgen(uint32_t x) {
    return ex2h2(hmax2u(x, hmul2u(x, 0x32663266u)));   // 0x3266 = 0.2f16
}
// mask from 2 bits (bit0 -> low f16, bit1 -> high f16)
__device__ __forceinline__ uint32_t mk2(uint32_t u) {
    return (u & 1u) * 0xFFFFu + (u & 2u) * 0x7FFF8000u;
}
// two masked f16x2 -> packed e4m3x4 (bytes ascending m)
__device__ __forceinline__ uint32_t cvtq(uint32_t x, uint32_t y) {
    unsigned short lo, hi;
    asm("cvt.rn.satfinite.e4m3x2.f16x2 %0, %1;" : "=h"(lo) : "r"(x));
    asm("cvt.rn.satfinite.e4m3x2.f16x2 %0, %1;" : "=h"(hi) : "r"(y));
    uint32_t r;
    asm("prmt.b32 %0, %1, %2, 0x5410;" : "=r"(r) : "r"((uint32_t)lo), "r"((uint32_t)hi));
    return r;
}
#define MMAF8(acc, a0, a1, a2, a3, b0, b1)                                     \
    asm volatile("mma.sync.aligned.m16n8k32.row.col.f32.e4m3.e4m3.f32 "        \
                 "{%0,%1,%2,%3}, {%4,%5,%6,%7}, {%8,%9}, {%0,%1,%2,%3};"       \
                 : "+f"(acc[0]), "+f"(acc[1]), "+f"(acc[2]), "+f"(acc[3])      \
                 : "r"(a0), "r"(a1), "r"(a2), "r"(a3), "r"(b0), "r"(b1))

// ============================ tiny stage kernel ============================
__global__ void k_wfa(const float* __restrict__ Wf, const float* __restrict__ a) {
    int tid = threadIdx.x;
    if (tid < NH * 128) {
        int h = tid >> 7, f = tid & 127;
        const float* wp = Wf + ((size_t)h * 128 + f) * HD;
        const float* ap = a + h * HD;
        float s = 0.f;
#pragma unroll 8
        for (int d = 0; d < HD; d++) s += wp[d] * ap[d];
        g_wfa[tid] = s;
    }
}

// ============================ fused prep kernel ============================
// blocks [0,PB): pack A bitmask   (DRAM-bound)
// blocks [PB,PB+EB): E1 fp8-fragment + d   (FMA-bound)
// blocks [PB+EB, +SB): s
#define PB 768
#define EB 1024
#define SB 1024
__global__ __launch_bounds__(256) void k_prep(const float* __restrict__ E0,
                                              const float* __restrict__ We,
                                              const float* __restrict__ a,
                                              const float* __restrict__ F0,
                                              const int* __restrict__ A) {
    __shared__ float sh[128 * 12 + 64];
    const int bid = blockIdx.x;
    const int tid = threadIdx.x;

    if (bid < PB) {                       // ---------- pack ----------
        int lane = tid & 31;
        int gw = (bid * 256 + tid) >> 5;
        const int nw = (PB * 256) >> 5;
        for (int idx = gw; idx < (MM / 32) * (NN / 4); idx += nw) {
            int w = idx & 255;
            int n4 = idx >> 8;
            const int* base = A + (size_t)(n4 * 4) * MM + w * 32 + lane;
            int v0 = base[0];
            int v1 = base[MM];
            int v2 = base[2 * MM];
            int v3 = base[3 * MM];
            uint32_t b0 = __ballot_sync(0xffffffffu, v0 > 0);
            uint32_t b1 = __ballot_sync(0xffffffffu, v1 > 0);
            uint32_t b2 = __ballot_sync(0xffffffffu, v2 > 0);
            uint32_t b3 = __ballot_sync(0xffffffffu, v3 > 0);
            if (lane == 0) {
                uint32_t* dst = g_AbT + (size_t)w * NN + n4 * 4;
                dst[0] = b0; dst[1] = b1; dst[2] = b2; dst[3] = b3;
            }
        }
    } else if (bid < PB + EB) {           // ---------- e1 ----------
        float* E0t = sh;                  // [e][r] stride 12
        float* dpart = sh + 128 * 12;     // [8][8]
        int m0 = (bid - PB) * 8;
#pragma unroll
        for (int k = 0; k < 4; k++) {
            int idx = tid + k * 256;
            int e = idx & 127, r = idx >> 7;
            E0t[e * 12 + r] = E0[(size_t)(m0 + r) * 128 + e];
        }
        __syncthreads();

        int h = tid >> 6, j = tid & 63;
        float acc[8];
#pragma unroll
        for (int r = 0; r < 8; r++) acc[r] = 0.f;
        const float* Weh = We + (size_t)h * 128 * HD + j;
#pragma unroll 4
        for (int e = 0; e < 128; e++) {
            float w = Weh[(size_t)e * HD];
            float4 r03 = *(const float4*)&E0t[e * 12];
            float4 r47 = *(const float4*)&E0t[e * 12 + 4];
            acc[0] += r03.x * w; acc[1] += r03.y * w;
            acc[2] += r03.z * w; acc[3] += r03.w * w;
            acc[4] += r47.x * w; acc[5] += r47.y * w;
            acc[6] += r47.z * w; acc[7] += r47.w * w;
        }
        // pack to e4m3 fragment layout
        unsigned short c01, c23, c45, c67;
        asm("cvt.rn.satfinite.e4m3x2.f32 %0, %1, %2;" : "=h"(c01) : "f"(acc[1]), "f"(acc[0]));
        asm("cvt.rn.satfinite.e4m3x2.f32 %0, %1, %2;" : "=h"(c23) : "f"(acc[3]), "f"(acc[2]));
        asm("cvt.rn.satfinite.e4m3x2.f32 %0, %1, %2;" : "=h"(c45) : "f"(acc[5]), "f"(acc[4]));
        asm("cvt.rn.satfinite.e4m3x2.f32 %0, %1, %2;" : "=h"(c67) : "f"(acc[7]), "f"(acc[6]));
        uint32_t q0, q1;
        asm("prmt.b32 %0, %1, %2, 0x5410;" : "=r"(q0) : "r"((uint32_t)c01), "r"((uint32_t)c23));
        asm("prmt.b32 %0, %1, %2, 0x5410;" : "=r"(q1) : "r"((uint32_t)c45), "r"((uint32_t)c67));
        int ch = m0 >> 6, mb = (m0 >> 5) & 1, reg = (m0 >> 4) & 1, tg0 = (m0 >> 2) & 3;
        size_t fi = ((size_t)((h * 128 + ch) * 2 + mb) * 32 + (j & 7) * 4 + tg0) * 16
                    + (j >> 3) * 2 + reg;
        g_E1q[fi] = q0;
        g_E1q[fi + 16] = q1;

        float av = a[h * HD + j];
        float p[8];
#pragma unroll
        for (int r = 0; r < 8; r++) p[r] = acc[r] * av;
#pragma unroll
        for (int o = 16; o; o >>= 1)
#pragma unroll
            for (int r = 0; r < 8; r++) p[r] += __shfl_xor_sync(0xffffffffu, p[r], o);
        int lane = tid & 31, w = tid >> 5;
        if (lane == 0)
#pragma unroll
            for (int r = 0; r < 8; r++) dpart[w * 8 + r] = p[r];
        __syncthreads();
        if (tid < 32) {
            int h2 = tid >> 3, r = tid & 7;
            g_d[h2 * MM + m0 + r] =
                (dpart[(2 * h2) * 8 + r] + dpart[(2 * h2 + 1) * 8 + r]) * LOG2E;
        }
    } else {                              // ---------- s ----------
        if (tid < 256) { sh[tid] = g_wfa[tid]; sh[tid + 256] = g_wfa[tid + 256]; }
        __syncthreads();
        int warp = tid >> 5, lane = tid & 31;
        int n = (bid - PB - EB) * 8 + warp;
        const float* fp = F0 + (size_t)n * 128;
        float f0 = fp[lane], f1 = fp[lane + 32], f2 = fp[lane + 64], f3 = fp[lane + 96];
#pragma unroll
        for (int h = 0; h < NH; h++) {
            const float* wp = sh + h * 128;
            float s = f0 * wp[lane] + f1 * wp[lane + 32] +
                      f2 * wp[lane + 64] + f3 * wp[lane + 96];
#pragma unroll
            for (int o = 16; o; o >>= 1) s += __shfl_xor_sync(0xffffffffu, s, o);
            if (lane == 0) g_s[h * NN + n] = s * LOG2E;
        }
    }
}

// ============================ flash kernel ============================
// block = 128 n-rows x 1 head, 8 warps. Stream m in 64-chunks.
// fp8 m16n8k32 MMA: W generated in-register (f16x2 gen -> e4m3 pack),
// B operand pre-fragmented in gmem -> smem (80B lane stride, conflict-free),
// Z via extra MMA with B = ones(e4m3).
__global__ __launch_bounds__(256, 2) void k_flash() {
    __shared__ __align__(16) uint32_t bq[2][1280];   // [mb][lane][20] x2 buffers
    __shared__ uint32_t dsh[2][32];                  // f16x2 d-pairs

    const int t = threadIdx.x, lane = t & 31, wid = t >> 5;
    const int g = lane >> 2, tg = lane & 3;
    const int h = blockIdx.y;
    const int n0 = blockIdx.x * 128;
    const int rowa = n0 + wid * 16 + g, rowb = rowa + 8;
    const float saf = g_s[h * NN + rowa];
    const float sbf = g_s[h * NN + rowb];
    __half2 sa2h = __floats2half2_rn(saf, saf);
    __half2 sb2h = __floats2half2_rn(sbf, sbf);
    const uint32_t sa2 = *(uint32_t*)&sa2h, sb2 = *(uint32_t*)&sb2h;

    float acc[9][4];
#pragma unroll
    for (int i = 0; i < 9; i++)
#pragma unroll
        for (int q = 0; q < 4; q++) acc[i][q] = 0.f;

    const uint32_t* Eq = g_E1q + (size_t)h * 128 * 1024;
    const float* dh = g_d + h * MM;
    const int smoff = (t >> 7) * 640 + ((t >> 2) & 31) * 20 + (t & 3) * 4;
    const uint32_t bones = 0x38383838u;              // e4m3 {1,1,1,1}

    // preload chunk 0
    {
        *(uint4*)&bq[0][smoff] = *(const uint4*)(Eq + t * 4);
        if (t < 16) {
            float4 dv = *(const float4*)(dh + t * 4);
            __half2 q0 = __floats2half2_rn(dv.x, dv.y);
            __half2 q1 = __floats2half2_rn(dv.z, dv.w);
            dsh[0][2 * t] = *(uint32_t*)&q0;
            dsh[0][2 * t + 1] = *(uint32_t*)&q1;
        }
    }
    uint32_t wa0 = g_AbT[rowa], wa1 = g_AbT[(size_t)NN + rowa];
    uint32_t wb0 = g_AbT[rowb], wb1 = g_AbT[(size_t)NN + rowb];
    __syncthreads();

    for (int ch = 0; ch < MM / 64; ch++) {
        const int b = ch & 1;
        const bool nxt = (ch + 1 < MM / 64);
        uint4 pf; float4 pd;
        uint32_t na0, na1, nb0, nb1;
        if (nxt) {
            pf = *(const uint4*)(Eq + (size_t)(ch + 1) * 1024 + t * 4);
            if (t < 16) pd = *(const float4*)(dh + (ch + 1) * 64 + t * 4);
            const size_t wbase = (size_t)(ch * 2 + 2) * NN;
            na0 = g_AbT[wbase + rowa];      na1 = g_AbT[wbase + NN + rowa];
            nb0 = g_AbT[wbase + rowb];      nb1 = g_AbT[wbase + NN + rowb];
        }

#pragma unroll
        for (int mb = 0; mb < 2; mb++) {
            const uint32_t ua = (mb ? wa1 : wa0) >> (4 * tg);
            const uint32_t ub = (mb ? wb1 : wb0) >> (4 * tg);
            const uint32_t dl01 = dsh[b][mb * 16 + 2 * tg];
            const uint32_t dl23 = dsh[b][mb * 16 + 2 * tg + 1];
            const uint32_t dh01 = dsh[b][mb * 16 + 8 + 2 * tg];
            const uint32_t dh23 = dsh[b][mb * 16 + 9 + 2 * tg];

            uint32_t pa0 = wgen(hadd2u(sa2, dl01)) & mk2(ua);
            uint32_t pa1 = wgen(hadd2u(sa2, dl23)) & mk2(ua >> 2);
            uint32_t pa2 = wgen(hadd2u(sa2, dh01)) & mk2(ua >> 16);
            uint32_t pa3 = wgen(hadd2u(sa2, dh23)) & mk2(ua >> 18);
            uint32_t pb0 = wgen(hadd2u(sb2, dl01)) & mk2(ub);
            uint32_t pb1 = wgen(hadd2u(sb2, dl23)) & mk2(ub >> 2);
            uint32_t pb2 = wgen(hadd2u(sb2, dh01)) & mk2(ub >> 16);
            uint32_t pb3 = wgen(hadd2u(sb2, dh23)) & mk2(ub >> 18);

            const uint32_t a0 = cvtq(pa0, pa1);
            const uint32_t a2 = cvtq(pa2, pa3);
            const uint32_t a1 = cvtq(pb0, pb1);
            const uint32_t a3 = cvtq(pb2, pb3);

            MMAF8(acc[8], a0, a1, a2, a3, bones, bones);   // Z

            const uint32_t* bp = &bq[b][mb * 640 + lane * 20];
#pragma unroll
            for (int p = 0; p < 4; p++) {
                uint4 bb = *(const uint4*)(bp + p * 4);
                MMAF8(acc[2 * p],     a0, a1, a2, a3, bb.x, bb.y);
                MMAF8(acc[2 * p + 1], a0, a1, a2, a3, bb.z, bb.w);
            }
        }

        if (nxt) {
            *(uint4*)&bq[b ^ 1][smoff] = pf;
            if (t < 16) {
                __half2 q0 = __floats2half2_rn(pd.x, pd.y);
                __half2 q1 = __floats2half2_rn(pd.z, pd.w);
                dsh[b ^ 1][2 * t] = *(uint32_t*)&q0;
                dsh[b ^ 1][2 * t + 1] = *(uint32_t*)&q1;
            }
            wa0 = na0; wa1 = na1; wb0 = nb0; wb1 = nb1;
        }
        __syncthreads();
    }

    // epilogue: per-head partials (race-free, each (h,n) owned by one block)
    float* npa = &g_np[h][rowa][0];
    float* npb = &g_np[h][rowb][0];
#pragma unroll
    for (int j = 0; j < 8; j++) {
        *(float2*)(npa + j * 8 + 2 * tg) = make_float2(acc[j][0], acc[j][1]);
        *(float2*)(npb + j * 8 + 2 * tg) = make_float2(acc[j][2], acc[j][3]);
    }
    if (tg == 0) { g_zp[h][rowa] = acc[8][0]; g_zp[h][rowb] = acc[8][2]; }
}

// combine heads: mean(num/Z) then softmax over 64 -> out
__global__ void k_comb(float* __restrict__ out) {
    int warp = threadIdx.x >> 5, lane = threadIdx.x & 31;
    int n = blockIdx.x * 8 + warp;
    float v0 = 0.f, v1 = 0.f;
#pragma unroll
    for (int h = 0; h < NH; h++) {
        float inv = 1.0f / g_zp[h][n];
        v0 += g_np[h][n][lane] * inv;
        v1 += g_np[h][n][lane + 32] * inv;
    }
    v0 *= 0.25f; v1 *= 0.25f;
    float mx = fmaxf(v0, v1);
#pragma unroll
    for (int o = 16; o; o >>= 1) mx = fmaxf(mx, __shfl_xor_sync(0xffffffffu, mx, o));
    float e0 = __expf(v0 - mx), e1 = __expf(v1 - mx);
    float s = e0 + e1;
#pragma unroll
    for (int o = 16; o; o >>= 1) s += __shfl_xor_sync(0xffffffffu, s, o);
    float r = 1.0f / s;
    out[(size_t)n * HD + lane] = e0 * r;
    out[(size_t)n * HD + 32 + lane] = e1 * r;
}

// ============================ launch ============================
extern "C" void kernel_launch(void* const* d_in, const int* in_sizes, int n_in,
                              void* d_out, int out_size) {
    const float* F0 = (const float*)d_in[0];
    const float* E0 = (const float*)d_in[1];
    const int*   A  = (const int*)d_in[2];
    const float* Wf = (const float*)d_in[3];
    const float* We = (const float*)d_in[4];
    const float* a  = (const float*)d_in[5];
    float* out = (float*)d_out;
    (void)in_sizes; (void)n_in; (void)out_size;

    k_wfa<<<1, 512>>>(Wf, a);
    k_prep<<<PB + EB + SB, 256>>>(E0, We, a, F0, A);
    k_flash<<<dim3(NN / 128, NH), 256>>>();
    k_comb<<<NN / 8, 256>>>(out);
}

// round 6
// speedup vs baseline: 1.1782x; 1.1782x over previous
#include <cuda_runtime.h>
#include <cuda_fp16.h>
#include <cstdint>

#define NN 8192
#define MM 8192
#define HD 64
#define NH 4
#define LOG2E 1.4426950408889634f

// ---- scratch (device globals; no allocations allowed) ----
__device__ float g_s[NH * NN];                              // pre-scaled by log2e
__device__ float g_d[NH * MM];                              // pre-scaled by log2e
__device__ float g_wfa[NH * 128];
__device__ __align__(16) __half g_E1h[(size_t)NH * MM * HD]; // [h][m][j] 4MB
__device__ uint32_t g_AbT[(size_t)(MM / 32) * NN];          // [m/32][n] 8MB
__device__ float g_np[NH][NN][HD];                          // per-head numerators 8MB
__device__ float g_zp[NH][NN];                              // per-head Z

__device__ __forceinline__ uint32_t smem_u32(const void* p) {
    uint32_t a;
    asm("{ .reg .u64 t; cvta.to.shared.u64 t, %1; cvt.u32.u64 %0, t; }" : "=r"(a) : "l"(p));
    return a;
}
__device__ __forceinline__ uint32_t hadd2u(uint32_t a, uint32_t b) {
    uint32_t r; asm("add.f16x2 %0,%1,%2;" : "=r"(r) : "r"(a), "r"(b)); return r;
}
__device__ __forceinline__ uint32_t hmul2u(uint32_t a, uint32_t b) {
    uint32_t r; asm("mul.f16x2 %0,%1,%2;" : "=r"(r) : "r"(a), "r"(b)); return r;
}
__device__ __forceinline__ uint32_t hmax2u(uint32_t a, uint32_t b) {
    uint32_t r; asm("max.f16x2 %0,%1,%2;" : "=r"(r) : "r"(a), "r"(b)); return r;
}
__device__ __forceinline__ uint32_t ex2h2(uint32_t a) {
    uint32_t r; asm("ex2.approx.f16x2 %0,%1;" : "=r"(r) : "r"(a)); return r;
}
// leaky_relu then exp2 on packed f16x2
__device__ __forceinline__ uint32_t wgen(uint32_t x) {
    return ex2h2(hmax2u(x, hmul2u(x, 0x32663266u)));   // 0x3266 = 0.2f16
}
// mask from 2 bits (bit0 -> low half, bit1 -> high half)
__device__ __forceinline__ uint32_t mk2(uint32_t u) {
    return (u & 1u) * 0xFFFFu + (u & 2u) * 0x7FFF8000u;
}
#define MMA16816(acc, a0, a1, a2, a3, b0, b1)                                  \
    asm volatile("mma.sync.aligned.m16n8k16.row.col.f32.f16.f16.f32 "          \
                 "{%0,%1,%2,%3}, {%4,%5,%6,%7}, {%8,%9}, {%0,%1,%2,%3};"       \
                 : "+f"(acc[0]), "+f"(acc[1]), "+f"(acc[2]), "+f"(acc[3])      \
                 : "r"(a0), "r"(a1), "r"(a2), "r"(a3), "r"(b0), "r"(b1))

// ============================ stage kernels ============================
// Pack A -> transposed bitmask. 4 independent rows per warp-iteration (MLP=4).
__global__ void k_pack(const int* __restrict__ A) {
    int lane = threadIdx.x & 31;
    int gw = (blockIdx.x * blockDim.x + threadIdx.x) >> 5;
    int nw = (gridDim.x * blockDim.x) >> 5;
    for (int idx = gw; idx < (MM / 32) * (NN / 4); idx += nw) {
        int w = idx & 255;           // MM/32 = 256
        int n4 = idx >> 8;
        const int* base = A + (size_t)(n4 * 4) * MM + w * 32 + lane;
        int v0 = base[0];
        int v1 = base[MM];
        int v2 = base[2 * MM];
        int v3 = base[3 * MM];
        uint32_t b0 = __ballot_sync(0xffffffffu, v0 > 0);
        uint32_t b1 = __ballot_sync(0xffffffffu, v1 > 0);
        uint32_t b2 = __ballot_sync(0xffffffffu, v2 > 0);
        uint32_t b3 = __ballot_sync(0xffffffffu, v3 > 0);
        if (lane == 0) {
            uint32_t* dst = g_AbT + (size_t)w * NN + n4 * 4;
            dst[0] = b0; dst[1] = b1; dst[2] = b2; dst[3] = b3;
        }
    }
}

// wfa[h,f] = sum_d Wf[h,f,d] * a[h,d]
__global__ void k_wfa(const float* __restrict__ Wf, const float* __restrict__ a) {
    int tid = threadIdx.x;
    if (tid < NH * 128) {
        int h = tid >> 7, f = tid & 127;
        const float* wp = Wf + ((size_t)h * 128 + f) * HD;
        const float* ap = a + h * HD;
        float s = 0.f;
#pragma unroll 8
        for (int d = 0; d < HD; d++) s += wp[d] * ap[d];
        g_wfa[tid] = s;
    }
}

// s[h,n] = (F0[n,:] . wfa[h,:]) * log2e
__global__ void k_s(const float* __restrict__ F0) {
    int warp = threadIdx.x >> 5, lane = threadIdx.x & 31;
    int gw = blockIdx.x * 8 + warp;
    int n = gw & (NN - 1), h = gw >> 13;
    const float* fp = F0 + (size_t)n * 128;
    const float* wp = g_wfa + h * 128;
    float s = 0.f;
#pragma unroll
    for (int k = 0; k < 4; k++) { int f = lane + k * 32; s += fp[f] * wp[f]; }
#pragma unroll
    for (int o = 16; o; o >>= 1) s += __shfl_xor_sync(0xffffffffu, s, o);
    if (lane == 0) g_s[h * NN + n] = s * LOG2E;
}

// E1h[h][m][j] (f16) and d[h][m]*log2e. 8 m-rows per block, E0 transposed in smem.
__global__ __launch_bounds__(256) void k_e1(const float* __restrict__ E0,
                                            const float* __restrict__ We,
                                            const float* __restrict__ a) {
    __shared__ float E0t[128 * 12];      // [e][r], stride 12 (16B-aligned float4)
    __shared__ float dpart[8][8];
    int m0 = blockIdx.x * 8;
    int tid = threadIdx.x;
#pragma unroll
    for (int k = 0; k < 4; k++) {
        int idx = tid + k * 256;         // 1024 elements
        int e = idx & 127, r = idx >> 7;
        E0t[e * 12 + r] = E0[(size_t)(m0 + r) * 128 + e];
    }
    __syncthreads();

    int h = tid >> 6, j = tid & 63;
    float acc[8];
#pragma unroll
    for (int r = 0; r < 8; r++) acc[r] = 0.f;
    const float* Weh = We + (size_t)h * 128 * HD + j;
#pragma unroll 4
    for (int e = 0; e < 128; e++) {
        float w = Weh[(size_t)e * HD];
        float4 r03 = *(const float4*)&E0t[e * 12];
        float4 r47 = *(const float4*)&E0t[e * 12 + 4];
        acc[0] += r03.x * w; acc[1] += r03.y * w;
        acc[2] += r03.z * w; acc[3] += r03.w * w;
        acc[4] += r47.x * w; acc[5] += r47.y * w;
        acc[6] += r47.z * w; acc[7] += r47.w * w;
    }
#pragma unroll
    for (int r = 0; r < 8; r++)
        g_E1h[((size_t)h * MM + m0 + r) * HD + j] = __float2half_rn(acc[r]);

    float av = a[h * HD + j];
    float p[8];
#pragma unroll
    for (int r = 0; r < 8; r++) p[r] = acc[r] * av;
#pragma unroll
    for (int o = 16; o; o >>= 1)
#pragma unroll
        for (int r = 0; r < 8; r++) p[r] += __shfl_xor_sync(0xffffffffu, p[r], o);
    int lane = tid & 31, w = tid >> 5;
    if (lane == 0)
#pragma unroll
        for (int r = 0; r < 8; r++) dpart[w][r] = p[r];
    __syncthreads();
    if (tid < 32) {
        int h2 = tid >> 3, r = tid & 7;
        g_d[h2 * MM + m0 + r] = (dpart[2 * h2][r] + dpart[2 * h2 + 1][r]) * LOG2E;
    }
}

// ============================ flash kernel ============================
// block = 128 n-rows x 1 head, 8 warps (16 rows each). Stream m in 128-wide
// STAGES (2x the old chunk): 72 MMAs + 32 LDSM + 8 gen-groups between barriers
// for much better latency overlap. f16x2 in-register W generation; B via
// ldmatrix.x4 from double-buffered E1 stage; Z via extra MMA with B = ones.
__global__ __launch_bounds__(256, 2) void k_flash() {
    __shared__ __align__(16) __half Et[2][128 * 72];   // 144B row stride, 36.9KB
    __shared__ uint32_t dsh[2][64];                    // f16x2 d-pairs (128 m)

    const int t = threadIdx.x, lane = t & 31, wid = t >> 5;
    const int g = lane >> 2, tg = lane & 3;
    const int h = blockIdx.y;
    const int n0 = blockIdx.x * 128;
    const int rowa = n0 + wid * 16 + g, rowb = rowa + 8;
    const float saf = g_s[h * NN + rowa];
    const float sbf = g_s[h * NN + rowb];
    __half2 sa2h = __floats2half2_rn(saf, saf);
    __half2 sb2h = __floats2half2_rn(sbf, sbf);
    const uint32_t sa2 = *(uint32_t*)&sa2h, sb2 = *(uint32_t*)&sb2h;

    float acc[9][4];
#pragma unroll
    for (int i = 0; i < 9; i++)
#pragma unroll
        for (int q = 0; q < 4; q++) acc[i][q] = 0.f;

    const __half* E1p = g_E1h + (size_t)h * MM * HD;
    const float* dh = g_d + h * MM;
    const uint32_t et0 = smem_u32(&Et[0][0]);
    const int lr16 = lane & 15, ct = lane >> 4;        // ldmatrix.x4 mapping
    const uint32_t bones = 0x3C003C00u;                // f16x2 {1,1}

    uint32_t wa[4], wb[4];

    // preload stage 0: 128 rows x 64 cols f16 (4 uint4 per thread) + d + masks
#pragma unroll
    for (int k = 0; k < 4; k++) {
        int idx = t + k * 256;             // 1024 uint4
        int row = idx >> 3, c8 = idx & 7;
        *(uint4*)((char*)&Et[0][0] + row * 144 + c8 * 16) =
            *(const uint4*)(E1p + (size_t)row * HD + c8 * 8);
    }
    if (t < 32) {
        float4 dv = *(const float4*)(dh + t * 4);
        __half2 q0 = __floats2half2_rn(dv.x, dv.y);
        __half2 q1 = __floats2half2_rn(dv.z, dv.w);
        dsh[0][2 * t] = *(uint32_t*)&q0;
        dsh[0][2 * t + 1] = *(uint32_t*)&q1;
    }
#pragma unroll
    for (int w = 0; w < 4; w++) {
        wa[w] = g_AbT[(size_t)w * NN + rowa];
        wb[w] = g_AbT[(size_t)w * NN + rowb];
    }
    __syncthreads();

    for (int st = 0; st < MM / 128; st++) {
        const int b = st & 1;
        const bool nxt = (st + 1 < MM / 128);
        uint4 pf[4]; float4 pd;
        uint32_t na[4], nb[4];
        if (nxt) {
            const __half* src = E1p + (size_t)(st + 1) * 128 * HD;
#pragma unroll
            for (int k = 0; k < 4; k++) {
                int idx = t + k * 256;
                pf[k] = *(const uint4*)(src + (size_t)(idx >> 3) * HD + (idx & 7) * 8);
            }
            if (t < 32) pd = *(const float4*)(dh + (st + 1) * 128 + t * 4);
            const size_t wbase = (size_t)(st + 1) * 4 * NN;
#pragma unroll
            for (int w = 0; w < 4; w++) {
                na[w] = g_AbT[wbase + (size_t)w * NN + rowa];
                nb[w] = g_AbT[wbase + (size_t)w * NN + rowb];
            }
        }

        const uint32_t etb = et0 + b * 18432;

#pragma unroll
        for (int mc = 0; mc < 8; mc++) {
            const uint32_t dp0 = dsh[b][mc * 8 + tg];
            const uint32_t dp1 = dsh[b][mc * 8 + tg + 4];
            const int sh = ((mc & 1) << 4) + 2 * tg;
            const uint32_t ua = wa[mc >> 1] >> sh;
            const uint32_t ub = wb[mc >> 1] >> sh;

            uint32_t a0 = wgen(hadd2u(sa2, dp0)) & mk2(ua);
            uint32_t a1 = wgen(hadd2u(sb2, dp0)) & mk2(ub);
            uint32_t a2 = wgen(hadd2u(sa2, dp1)) & mk2(ua >> 8);
            uint32_t a3 = wgen(hadd2u(sb2, dp1)) & mk2(ub >> 8);

            MMA16816(acc[8], a0, a1, a2, a3, bones, bones);   // Z

            const uint32_t rb = etb + (mc * 16 + lr16) * 144 + ct * 16;
#pragma unroll
            for (int jj = 0; jj < 4; jj++) {
                uint32_t f0, f1, f2, f3;
                asm volatile("ldmatrix.sync.aligned.m8n8.x4.trans.shared.b16 "
                             "{%0,%1,%2,%3}, [%4];"
                             : "=r"(f0), "=r"(f1), "=r"(f2), "=r"(f3)
                             : "r"(rb + jj * 32));
                MMA16816(acc[2 * jj],     a0, a1, a2, a3, f0, f1);
                MMA16816(acc[2 * jj + 1], a0, a1, a2, a3, f2, f3);
            }
        }

        if (nxt) {
            char* dst = (char*)&Et[b ^ 1][0];
#pragma unroll
            for (int k = 0; k < 4; k++) {
                int idx = t + k * 256;
                *(uint4*)(dst + (idx >> 3) * 144 + (idx & 7) * 16) = pf[k];
            }
            if (t < 32) {
                __half2 q0 = __floats2half2_rn(pd.x, pd.y);
                __half2 q1 = __floats2half2_rn(pd.z, pd.w);
                dsh[b ^ 1][2 * t] = *(uint32_t*)&q0;
                dsh[b ^ 1][2 * t + 1] = *(uint32_t*)&q1;
            }
#pragma unroll
            for (int w = 0; w < 4; w++) { wa[w] = na[w]; wb[w] = nb[w]; }
        }
        __syncthreads();
    }

    // epilogue: per-head partials (race-free, each (h,n) owned by one block)
    float* npa = &g_np[h][rowa][0];
    float* npb = &g_np[h][rowb][0];
#pragma unroll
    for (int j = 0; j < 8; j++) {
        *(float2*)(npa + j * 8 + 2 * tg) = make_float2(acc[j][0], acc[j][1]);
        *(float2*)(npb + j * 8 + 2 * tg) = make_float2(acc[j][2], acc[j][3]);
    }
    if (tg == 0) { g_zp[h][rowa] = acc[8][0]; g_zp[h][rowb] = acc[8][2]; }
}

// combine heads: mean(num/Z) then softmax over 64 -> out
__global__ void k_comb(float* __restrict__ out) {
    int warp = threadIdx.x >> 5, lane = threadIdx.x & 31;
    int n = blockIdx.x * 8 + warp;
    float v0 = 0.f, v1 = 0.f;
#pragma unroll
    for (int h = 0; h < NH; h++) {
        float inv = 1.0f / g_zp[h][n];
        v0 += g_np[h][n][lane] * inv;
        v1 += g_np[h][n][lane + 32] * inv;
    }
    v0 *= 0.25f; v1 *= 0.25f;
    float mx = fmaxf(v0, v1);
#pragma unroll
    for (int o = 16; o; o >>= 1) mx = fmaxf(mx, __shfl_xor_sync(0xffffffffu, mx, o));
    float e0 = __expf(v0 - mx), e1 = __expf(v1 - mx);
    float s = e0 + e1;
#pragma unroll
    for (int o = 16; o; o >>= 1) s += __shfl_xor_sync(0xffffffffu, s, o);
    float r = 1.0f / s;
    out[(size_t)n * HD + lane] = e0 * r;
    out[(size_t)n * HD + 32 + lane] = e1 * r;
}

// ============================ launch ============================
extern "C" void kernel_launch(void* const* d_in, const int* in_sizes, int n_in,
                              void* d_out, int out_size) {
    const float* F0 = (const float*)d_in[0];
    const float* E0 = (const float*)d_in[1];
    const int*   A  = (const int*)d_in[2];
    const float* Wf = (const float*)d_in[3];
    const float* We = (const float*)d_in[4];
    const float* a  = (const float*)d_in[5];
    float* out = (float*)d_out;
    (void)in_sizes; (void)n_in; (void)out_size;

    k_pack<<<2048, 256>>>(A);
    k_wfa<<<1, 512>>>(Wf, a);
    k_s<<<4096, 256>>>(F0);
    k_e1<<<MM / 8, 256>>>(E0, We, a);
    k_flash<<<dim3(NN / 128, NH), 256>>>();
    k_comb<<<NN / 8, 256>>>(out);
}